// round 9
// baseline (speedup 1.0000x reference)
#include <cuda_runtime.h>
#include <math.h>
#include <stdint.h>

#define NTOK   20
#define DVEC   256
#define KSAMP  4096
#define NSTEP  19
#define ROWN   (KSAMP*NTOK)        /* 81920 keys per step */
#define SCAN_TPB 32
#define SCAN_BLK (KSAMP/SCAN_TPB)  /* 128 blocks, 1 warp each */

__device__ float          g_S[NTOK*6];        // [i][0..2]=x.Wf+b, [3..5]=x.Wa
__device__ uint32_t       g_key[NSTEP*ROWN];  // TRANSPOSED: [t][j][k]
__device__ unsigned char  g_opsT[KSAMP*20];   // ops transposed: [k][t]
__device__ float          g_score[KSAMP];
__device__ unsigned char  g_legal[KSAMP];
__device__ unsigned int   g_gmax_u = 0;       // int-mapped float max (reset)
__device__ int            g_cnt = 0;          // legal count (reset)
__device__ int            g_blocks_done = 0;  // reset by last scan block

// ---------------- Threefry-2x32 (20 rounds), identical to JAX ----------------
__host__ __device__ __forceinline__ void tf_block(uint32_t k0, uint32_t k1,
                                                  uint32_t x0, uint32_t x1,
                                                  uint32_t* o0, uint32_t* o1) {
  uint32_t ks2 = k0 ^ k1 ^ 0x1BD11BDAu;
  x0 += k0; x1 += k1;
#define TF_ROT(r) { x0 += x1; x1 = (x1 << (r)) | (x1 >> (32 - (r))); x1 ^= x0; }
  TF_ROT(13) TF_ROT(15) TF_ROT(26) TF_ROT(6)
  x0 += k1;  x1 += ks2 + 1u;
  TF_ROT(17) TF_ROT(29) TF_ROT(16) TF_ROT(24)
  x0 += ks2; x1 += k0 + 2u;
  TF_ROT(13) TF_ROT(15) TF_ROT(26) TF_ROT(6)
  x0 += k0;  x1 += k1 + 3u;
  TF_ROT(17) TF_ROT(29) TF_ROT(16) TF_ROT(24)
  x0 += k1;  x1 += ks2 + 4u;
  TF_ROT(13) TF_ROT(15) TF_ROT(26) TF_ROT(6)
  x0 += ks2; x1 += k0 + 5u;
#undef TF_ROT
  *o0 = x0; *o1 = x1;
}

__device__ __forceinline__ uint32_t tf_bits32(uint32_t k0, uint32_t k1, uint32_t i) {
  uint32_t a, b;
  tf_block(k0, k1, 0u, i, &a, &b);
  return a ^ b;
}

// ---------------- warp-per-token prep (lane owns 8 dims, shuffle-only) --------
__device__ __forceinline__ void prep_token(int i, int lane,
                                           const int* __restrict__ ids,
                                           const float* __restrict__ emb,
                                           const float* __restrict__ lv,
                                           const float* __restrict__ fx,
                                           const float* __restrict__ Wf,
                                           const float* __restrict__ Wa,
                                           const float* __restrict__ bop) {
  const unsigned FULL = 0xFFFFFFFFu;
  int id = ids[i];
  const float4* er = (const float4*)(emb + (size_t)id * DVEC);
  const float4* fr = (const float4*)(fx  + (size_t)id * DVEC);
  float4 e0 = er[lane * 2], e1 = er[lane * 2 + 1];
  float4 f0 = fr[lane * 2], f1 = fr[lane * 2 + 1];
  float lvv = lv[id];

  float ev[8] = {e0.x, e0.y, e0.z, e0.w, e1.x, e1.y, e1.z, e1.w};
  float fv[8] = {f0.x, f0.y, f0.z, f0.w, f1.x, f1.y, f1.z, f1.w};

  float m = ev[0];
#pragma unroll
  for (int j = 1; j < 8; j++) m = fmaxf(m, ev[j]);
#pragma unroll
  for (int o = 16; o; o >>= 1) m = fmaxf(m, __shfl_xor_sync(FULL, m, o));

  float ex[8]; float sm = 0.0f;
#pragma unroll
  for (int j = 0; j < 8; j++) { ex[j] = expf(ev[j] - m); sm += ex[j]; }
#pragma unroll
  for (int o = 16; o; o >>= 1) sm += __shfl_xor_sync(FULL, sm, o);

  float x[8];
#pragma unroll
  for (int j = 0; j < 8; j++) x[j] = (ex[j] / sm) * lvv + fv[j];

  float p[6] = {0, 0, 0, 0, 0, 0};
#pragma unroll
  for (int j = 0; j < 8; j++) {
    int d = lane * 8 + j;
    p[0] += x[j] * Wf[d * 3 + 0];
    p[1] += x[j] * Wf[d * 3 + 1];
    p[2] += x[j] * Wf[d * 3 + 2];
    p[3] += x[j] * Wa[d * 3 + 0];
    p[4] += x[j] * Wa[d * 3 + 1];
    p[5] += x[j] * Wa[d * 3 + 2];
  }
#pragma unroll
  for (int o = 16; o; o >>= 1) {
#pragma unroll
    for (int q = 0; q < 6; q++) p[q] += __shfl_xor_sync(FULL, p[q], o);
  }
  if (lane == 0) {
#pragma unroll
    for (int q = 0; q < 6; q++)
      g_S[i * 6 + q] = p[q] + (q < 3 ? bop[q] : 0.0f);
  }
}

// ---------------- Kernel 1: keygen (transposed) + ops + prep ------------------
// y in [0,18]: packed sort keys, stored g_key[y][j][k] (linear writes).
// y == 19   : ops (x<304), prep (x in 304..306).
__global__ __launch_bounds__(256) void keygen_kernel(
    uint32_t kg0, uint32_t kg1, uint32_t kop0, uint32_t kop1,
    const int* __restrict__ ids, const float* __restrict__ emb,
    const float* __restrict__ lv, const float* __restrict__ fx,
    const float* __restrict__ Wf, const float* __restrict__ Wa,
    const float* __restrict__ bop) {
  int y = blockIdx.y;
  int tid = threadIdx.x;

  if (y == NSTEP) {
    if (blockIdx.x < 304) {                  // ops: n = t*4096 + k
      int n = blockIdx.x * 256 + tid;
      uint32_t bits = tf_bits32(kop0, kop1, (uint32_t)n);
      uint32_t op = ((bits >> 16) % 3u + (bits & 0xFFFFu) % 3u) % 3u;
      int t = n >> 12, k = n & 4095;
      g_opsT[k * 20 + t] = (unsigned char)op;
    } else if (blockIdx.x < 307) {           // prep: 20 token-warps
      int wf = (blockIdx.x - 304) * 8 + (tid >> 5);
      if (wf < NTOK)
        prep_token(wf, tid & 31, ids, emb, lv, fx, Wf, Wa, bop);
    }
    return;
  }

  int n = blockIdx.x * 256 + tid;            // 0..81919, n = j*4096 + k
  int j = n >> 12;                           // slot 0..19
  int k = n & 4095;                          // sample
  // JAX counter for gumbel[t][k][j]:
  uint32_t ctr = (uint32_t)y * (uint32_t)ROWN + (uint32_t)k * 20u + (uint32_t)j;
  uint32_t key = tf_bits32(kg0, kg1, ctr) >> 9;  // gumbel order == bits>>9 order
  g_key[y * ROWN + n] = ((key + 1u) << 5) | (31u - (uint32_t)j);
}

// ---------------- Kernel 2: thread-per-sample scan (coalesced) + reduce -------
__global__ __launch_bounds__(SCAN_TPB) void scan_kernel(float* __restrict__ out) {
  __shared__ float sS[NTOK * 6];
  const unsigned FULL = 0xFFFFFFFFu;
  int tid = threadIdx.x;
  int k = blockIdx.x * SCAN_TPB + tid;       // sample 0..4095

#pragma unroll
  for (int q = tid; q < NTOK * 6; q += SCAN_TPB) sS[q] = g_S[q];
  __syncwarp();

  // ops: 19 bytes at g_opsT[k*20] (5 u32 loads)
  uint32_t ow[5];
  {
    const uint32_t* p = (const uint32_t*)(g_opsT + k * 20);
#pragma unroll
    for (int q = 0; q < 5; q++) ow[q] = p[q];
  }

  // rolling key buffers; loads coalesced across the warp (consecutive k)
  uint32_t cur[NTOK], nxt[NTOK];
#pragma unroll
  for (int j = 0; j < NTOK; j++) cur[j] = g_key[j * KSAMP + k];

  unsigned avail = 0xFFFFFu, f1 = 0u, f2 = 0u;
  // ptr[20] packed 5 bits/slot (init ptr[j]=j)
  unsigned long long plo = 0ull, phi = 0ull;
#pragma unroll
  for (int j = 0; j < 12; j++) plo |= (unsigned long long)j << (5 * j);
#pragma unroll
  for (int j = 12; j < 20; j++) phi |= (unsigned long long)j << (5 * (j - 12));

  float score = 0.0f;
  bool legal = true;

#pragma unroll
  for (int t = 0; t < NSTEP; t++) {
    // prefetch next step first (latency overlaps this step's ALU chain)
    if (t + 1 < NSTEP) {
#pragma unroll
      for (int j = 0; j < NTOK; j++)
        nxt[j] = g_key[(t + 1) * ROWN + j * KSAMP + k];
    }

    // masked top-2 over packed keys (value order + exact jax tie-break)
    uint32_t u1 = 0u, u2 = 0u;
#pragma unroll
    for (int j = 0; j < NTOK; j++) {
      uint32_t v = ((avail >> j) & 1u) ? cur[j] : 0u;
      uint32_t mn = min(u1, v);
      u1 = max(u1, v);
      u2 = max(u2, mn);
    }
    int b1 = (int)((~u1) & 31u), b2 = (int)((~u2) & 31u);
    avail &= ~(1u << b2);

    int op = (int)((ow[t >> 2] >> ((t & 3) * 8)) & 3u);

    int s1 = 5 * b1, s2 = 5 * b2;
    int s1l = (s1 < 60) ? s1 : 0,  s1h = (s1 >= 60) ? s1 - 60 : 0;
    int s2l = (s2 < 60) ? s2 : 0,  s2h = (s2 >= 60) ? s2 - 60 : 0;
    int pf = (int)((b1 < 12 ? (plo >> s1l) : (phi >> s1h)) & 31ull);
    int pa = (int)((b2 < 12 ? (plo >> s2l) : (phi >> s2h)) & 31ull);
    score += sS[pf * 6 + op] + sS[pa * 6 + 3 + op];

    unsigned of1 = (f1 >> b1) & 1u;
    unsigned of2 = (f2 >> b1) & 1u;
    bool bad = ((op != 2) && of1) || ((op == 1) && of2);
    legal = legal && !bad;

    if (op == 2) {                           // mod: slot b1 := copy of slot b2
      if (b1 < 12) plo = (plo & ~(31ull << s1l)) | ((unsigned long long)pa << s1l);
      else         phi = (phi & ~(31ull << s1h)) | ((unsigned long long)pa << s1h);
      unsigned a1 = (f1 >> b2) & 1u, a2 = (f2 >> b2) & 1u;
      f1 = (f1 & ~(1u << b1)) | (a1 << b1);
      f2 = (f2 & ~(1u << b1)) | (a2 << b1);
    } else if (op == 0) {
      f1 |= 1u << b1;
    } else {
      f2 |= 1u << b1;
    }

    if (t + 1 < NSTEP) {
#pragma unroll
      for (int j = 0; j < NTOK; j++) cur[j] = nxt[j];   // renamed, free
    }
  }

  g_score[k] = score;
  g_legal[k] = legal ? 1 : 0;

  // warp partials -> global atomics (max exact, count exact)
  float lm = legal ? score : -INFINITY;
  int lc = legal ? 1 : 0;
#pragma unroll
  for (int o = 16; o; o >>= 1) {
    lm = fmaxf(lm, __shfl_xor_sync(FULL, lm, o));
    lc += __shfl_xor_sync(FULL, lc, o);
  }
  int last = 0;
  if (tid == 0) {
    if (lc > 0) {
      int s = __float_as_int(lm);
      unsigned enc = (unsigned)s ^ (((unsigned)(s >> 31)) | 0x80000000u);
      atomicMax(&g_gmax_u, enc);
    }
    atomicAdd(&g_cnt, lc);
    __threadfence();
    last = (atomicAdd(&g_blocks_done, 1) == SCAN_BLK - 1);
  }
  last = __shfl_sync(FULL, last, 0);
  if (!last) return;
  __threadfence();                           // acquire scores/legal/max/cnt

  unsigned genc = g_gmax_u;
  int cnt = g_cnt;
  int gs = (genc & 0x80000000u) ? (int)(genc ^ 0x80000000u) : (int)(~genc);
  float gm = __int_as_float(gs);

  float sum = 0.0f;
  int q0 = tid * (KSAMP / SCAN_TPB);
#pragma unroll 8
  for (int q = 0; q < KSAMP / SCAN_TPB; q += 4) {
    float4 sc = *(const float4*)(g_score + q0 + q);
    uchar4 lg = *(const uchar4*)(g_legal + q0 + q);
    if (lg.x) sum += __expf(sc.x - gm);
    if (lg.y) sum += __expf(sc.y - gm);
    if (lg.z) sum += __expf(sc.z - gm);
    if (lg.w) sum += __expf(sc.w - gm);
  }
#pragma unroll
  for (int o = 16; o; o >>= 1) sum += __shfl_xor_sync(FULL, sum, o);

  if (tid == 0) {
    float lse = gm + logf(sum);
    double log_all = lgamma(21.0) + log(1767263190.0) + 19.0 * log(3.0);
    double res = log_all + (double)logf((float)cnt) - 2.0 * log(4096.0) + (double)lse;
    out[0] = (float)res;
    g_blocks_done = 0;                       // reset for next graph replay
    g_cnt = 0;
    g_gmax_u = 0u;
  }
}

// ---------------- Launch ------------------------------------------------------
extern "C" void kernel_launch(void* const* d_in, const int* in_sizes, int n_in,
                              void* d_out, int out_size) {
  const int*   ids = (const int*)d_in[0];
  const float* emb = (const float*)d_in[1];
  const float* lv  = (const float*)d_in[2];
  const float* fx  = (const float*)d_in[3];
  const float* Wf  = (const float*)d_in[4];
  const float* Wa  = (const float*)d_in[5];
  const float* bop = (const float*)d_in[6];
  float* out = (float*)d_out;

  // jax.random.key(42) -> (0,42); partitionable foldlike split
  uint32_t kop0, kop1, kg0, kg1;
  tf_block(0u, 42u, 0u, 0u, &kop0, &kop1);
  tf_block(0u, 42u, 0u, 1u, &kg0, &kg1);

  keygen_kernel<<<dim3(ROWN / 256, NSTEP + 1), 256>>>(kg0, kg1, kop0, kop1,
                                                      ids, emb, lv, fx, Wf, Wa, bop);
  scan_kernel<<<SCAN_BLK, SCAN_TPB>>>(out);
}

// round 10
// speedup vs baseline: 1.2294x; 1.2294x over previous
#include <cuda_runtime.h>
#include <math.h>
#include <stdint.h>

#define NTOK   20
#define DVEC   256
#define KSAMP  4096
#define NSTEP  19
#define ROWN   (KSAMP*NTOK)        /* 81920 keys per step */
#define SCAN_TPB 128               /* 4 warps = 32 samples per block */
#define SCAN_BLK (KSAMP/32)        /* 128 blocks */

__device__ float          g_S[NTOK*6];        // [i][0..2]=x.Wf+b, [3..5]=x.Wa
__device__ uint32_t       g_key[NSTEP*ROWN];  // TRANSPOSED: [t][j][k]
__device__ unsigned char  g_opsT[KSAMP*20];   // ops transposed: [k][t]
__device__ float          g_score[KSAMP];
__device__ unsigned char  g_legal[KSAMP];
__device__ unsigned int   g_gmax_u = 0;       // int-mapped float max (reset)
__device__ int            g_cnt = 0;          // legal count (reset)
__device__ int            g_blocks_done = 0;  // reset by last scan block

// ---------------- Threefry-2x32 (20 rounds), identical to JAX ----------------
__host__ __device__ __forceinline__ void tf_block(uint32_t k0, uint32_t k1,
                                                  uint32_t x0, uint32_t x1,
                                                  uint32_t* o0, uint32_t* o1) {
  uint32_t ks2 = k0 ^ k1 ^ 0x1BD11BDAu;
  x0 += k0; x1 += k1;
#define TF_ROT(r) { x0 += x1; x1 = (x1 << (r)) | (x1 >> (32 - (r))); x1 ^= x0; }
  TF_ROT(13) TF_ROT(15) TF_ROT(26) TF_ROT(6)
  x0 += k1;  x1 += ks2 + 1u;
  TF_ROT(17) TF_ROT(29) TF_ROT(16) TF_ROT(24)
  x0 += ks2; x1 += k0 + 2u;
  TF_ROT(13) TF_ROT(15) TF_ROT(26) TF_ROT(6)
  x0 += k0;  x1 += k1 + 3u;
  TF_ROT(17) TF_ROT(29) TF_ROT(16) TF_ROT(24)
  x0 += k1;  x1 += ks2 + 4u;
  TF_ROT(13) TF_ROT(15) TF_ROT(26) TF_ROT(6)
  x0 += ks2; x1 += k0 + 5u;
#undef TF_ROT
  *o0 = x0; *o1 = x1;
}

__device__ __forceinline__ uint32_t tf_bits32(uint32_t k0, uint32_t k1, uint32_t i) {
  uint32_t a, b;
  tf_block(k0, k1, 0u, i, &a, &b);
  return a ^ b;
}

// ---------------- warp-per-token prep (lane owns 8 dims, shuffle-only) --------
__device__ __forceinline__ void prep_token(int i, int lane,
                                           const int* __restrict__ ids,
                                           const float* __restrict__ emb,
                                           const float* __restrict__ lv,
                                           const float* __restrict__ fx,
                                           const float* __restrict__ Wf,
                                           const float* __restrict__ Wa,
                                           const float* __restrict__ bop) {
  const unsigned FULL = 0xFFFFFFFFu;
  int id = ids[i];
  const float4* er = (const float4*)(emb + (size_t)id * DVEC);
  const float4* fr = (const float4*)(fx  + (size_t)id * DVEC);
  float4 e0 = er[lane * 2], e1 = er[lane * 2 + 1];
  float4 f0 = fr[lane * 2], f1 = fr[lane * 2 + 1];
  float lvv = lv[id];

  float ev[8] = {e0.x, e0.y, e0.z, e0.w, e1.x, e1.y, e1.z, e1.w};
  float fv[8] = {f0.x, f0.y, f0.z, f0.w, f1.x, f1.y, f1.z, f1.w};

  float m = ev[0];
#pragma unroll
  for (int j = 1; j < 8; j++) m = fmaxf(m, ev[j]);
#pragma unroll
  for (int o = 16; o; o >>= 1) m = fmaxf(m, __shfl_xor_sync(FULL, m, o));

  float ex[8]; float sm = 0.0f;
#pragma unroll
  for (int j = 0; j < 8; j++) { ex[j] = expf(ev[j] - m); sm += ex[j]; }
#pragma unroll
  for (int o = 16; o; o >>= 1) sm += __shfl_xor_sync(FULL, sm, o);

  float x[8];
#pragma unroll
  for (int j = 0; j < 8; j++) x[j] = (ex[j] / sm) * lvv + fv[j];

  float p[6] = {0, 0, 0, 0, 0, 0};
#pragma unroll
  for (int j = 0; j < 8; j++) {
    int d = lane * 8 + j;
    p[0] += x[j] * Wf[d * 3 + 0];
    p[1] += x[j] * Wf[d * 3 + 1];
    p[2] += x[j] * Wf[d * 3 + 2];
    p[3] += x[j] * Wa[d * 3 + 0];
    p[4] += x[j] * Wa[d * 3 + 1];
    p[5] += x[j] * Wa[d * 3 + 2];
  }
#pragma unroll
  for (int o = 16; o; o >>= 1) {
#pragma unroll
    for (int q = 0; q < 6; q++) p[q] += __shfl_xor_sync(FULL, p[q], o);
  }
  if (lane == 0) {
#pragma unroll
    for (int q = 0; q < 6; q++)
      g_S[i * 6 + q] = p[q] + (q < 3 ? bop[q] : 0.0f);
  }
}

// ---------------- Kernel 1: keygen (transposed) + ops + prep ------------------
__global__ __launch_bounds__(256) void keygen_kernel(
    uint32_t kg0, uint32_t kg1, uint32_t kop0, uint32_t kop1,
    const int* __restrict__ ids, const float* __restrict__ emb,
    const float* __restrict__ lv, const float* __restrict__ fx,
    const float* __restrict__ Wf, const float* __restrict__ Wa,
    const float* __restrict__ bop) {
  int y = blockIdx.y;
  int tid = threadIdx.x;

  if (y == NSTEP) {
    if (blockIdx.x < 304) {                  // ops: n = t*4096 + k
      int n = blockIdx.x * 256 + tid;
      uint32_t bits = tf_bits32(kop0, kop1, (uint32_t)n);
      uint32_t op = ((bits >> 16) % 3u + (bits & 0xFFFFu) % 3u) % 3u;
      int t = n >> 12, k = n & 4095;
      g_opsT[k * 20 + t] = (unsigned char)op;
    } else if (blockIdx.x < 307) {           // prep: 20 token-warps
      int wf = (blockIdx.x - 304) * 8 + (tid >> 5);
      if (wf < NTOK)
        prep_token(wf, tid & 31, ids, emb, lv, fx, Wf, Wa, bop);
    }
    return;
  }

  int n = blockIdx.x * 256 + tid;            // 0..81919, n = j*4096 + k
  int j = n >> 12;                           // slot 0..19
  int k = n & 4095;                          // sample
  // JAX counter for gumbel[t][k][j]:
  uint32_t ctr = (uint32_t)y * (uint32_t)ROWN + (uint32_t)k * 20u + (uint32_t)j;
  uint32_t key = tf_bits32(kg0, kg1, ctr) >> 9;  // gumbel order == bits>>9 order
  g_key[y * ROWN + n] = ((key + 1u) << 5) | (31u - (uint32_t)j);
}

// ---------------- Kernel 2: 4-lanes-per-sample scan + fused reduce ------------
// lane = 4*samp_in_warp + s; lane s owns slots [5s, 5s+5). Top-2 merged with
// 2 shfl_xor rounds (exact, tie-break in packed key). State replicated per lane.
__global__ __launch_bounds__(SCAN_TPB) void scan_kernel(float* __restrict__ out) {
  __shared__ float sS[NTOK * 6];
  __shared__ float sred[SCAN_TPB];
  __shared__ int   scnt[SCAN_TPB];
  const unsigned FULL = 0xFFFFFFFFu;
  int tid = threadIdx.x;
  int lane = tid & 31;
  int s = lane & 3;                          // sub-lane 0..3
  int j0 = s * 5;                            // first owned slot
  int k = blockIdx.x * 32 + (tid >> 5) * 8 + (lane >> 2);  // sample 0..4095

  for (int q = tid; q < NTOK * 6; q += SCAN_TPB) sS[q] = g_S[q];
  __syncthreads();

  // ops: 19 bytes at g_opsT[k*20] (5 u32 loads; 4 lanes same addr -> L1 bcast)
  uint32_t ow[5];
  {
    const uint32_t* p = (const uint32_t*)(g_opsT + k * 20);
#pragma unroll
    for (int q = 0; q < 5; q++) ow[q] = p[q];
  }

  uint32_t cur[5], nxt[5];
#pragma unroll
  for (int i = 0; i < 5; i++) cur[i] = g_key[(j0 + i) * KSAMP + k];

  unsigned avail = 0xFFFFFu, f1 = 0u, f2 = 0u;
  unsigned long long plo = 0ull, phi = 0ull;   // ptr[20], 5 bits/slot
#pragma unroll
  for (int j = 0; j < 12; j++) plo |= (unsigned long long)j << (5 * j);
#pragma unroll
  for (int j = 12; j < 20; j++) phi |= (unsigned long long)j << (5 * (j - 12));

  float score = 0.0f;
  bool legal = true;

#pragma unroll
  for (int t = 0; t < NSTEP; t++) {
    if (t + 1 < NSTEP) {
#pragma unroll
      for (int i = 0; i < 5; i++)
        nxt[i] = g_key[(t + 1) * ROWN + (j0 + i) * KSAMP + k];
    }

    // local masked top-2 over 5 owned slots
    uint32_t u1 = 0u, u2 = 0u;
#pragma unroll
    for (int i = 0; i < 5; i++) {
      uint32_t v = ((avail >> (j0 + i)) & 1u) ? cur[i] : 0u;
      uint32_t mn = min(u1, v);
      u1 = max(u1, v);
      u2 = max(u2, mn);
    }
    // merge across the 4 sub-lanes (serves all 8 samples in parallel)
#pragma unroll
    for (int o = 1; o <= 2; o <<= 1) {
      uint32_t o1 = __shfl_xor_sync(FULL, u1, o);
      uint32_t o2 = __shfl_xor_sync(FULL, u2, o);
      uint32_t lo = min(u1, o1);
      u1 = max(u1, o1);
      u2 = max(lo, max(u2, o2));
    }
    int b1 = (int)((~u1) & 31u), b2 = (int)((~u2) & 31u);
    avail &= ~(1u << b2);

    int op = (int)((ow[t >> 2] >> ((t & 3) * 8)) & 3u);

    int s1 = 5 * b1, s2 = 5 * b2;
    int s1l = (s1 < 60) ? s1 : 0,  s1h = (s1 >= 60) ? s1 - 60 : 0;
    int s2l = (s2 < 60) ? s2 : 0,  s2h = (s2 >= 60) ? s2 - 60 : 0;
    int pf = (int)((b1 < 12 ? (plo >> s1l) : (phi >> s1h)) & 31ull);
    int pa = (int)((b2 < 12 ? (plo >> s2l) : (phi >> s2h)) & 31ull);
    if (s == 0)
      score += sS[pf * 6 + op] + sS[pa * 6 + 3 + op];

    unsigned of1 = (f1 >> b1) & 1u;
    unsigned of2 = (f2 >> b1) & 1u;
    bool bad = ((op != 2) && of1) || ((op == 1) && of2);
    legal = legal && !bad;

    if (op == 2) {                           // mod: slot b1 := copy of slot b2
      if (b1 < 12) plo = (plo & ~(31ull << s1l)) | ((unsigned long long)pa << s1l);
      else         phi = (phi & ~(31ull << s1h)) | ((unsigned long long)pa << s1h);
      unsigned a1 = (f1 >> b2) & 1u, a2 = (f2 >> b2) & 1u;
      f1 = (f1 & ~(1u << b1)) | (a1 << b1);
      f2 = (f2 & ~(1u << b1)) | (a2 << b1);
    } else if (op == 0) {
      f1 |= 1u << b1;
    } else {
      f2 |= 1u << b1;
    }

    if (t + 1 < NSTEP) {
#pragma unroll
      for (int i = 0; i < 5; i++) cur[i] = nxt[i];
    }
  }

  if (s == 0) {
    g_score[k] = score;
    g_legal[k] = legal ? 1 : 0;
  }

  // block partials -> global atomics (max exact, count exact)
  float lm = (s == 0 && legal) ? score : -INFINITY;
  int lc = (s == 0 && legal) ? 1 : 0;
#pragma unroll
  for (int o = 16; o; o >>= 1) {
    lm = fmaxf(lm, __shfl_xor_sync(FULL, lm, o));
    lc += __shfl_xor_sync(FULL, lc, o);
  }
  if (lane == 0) { sred[tid >> 5] = lm; scnt[tid >> 5] = lc; }
  __syncthreads();
  int last = 0;
  if (tid == 0) {
    float bm = sred[0]; int bc = scnt[0];
#pragma unroll
    for (int q = 1; q < SCAN_TPB / 32; q++) { bm = fmaxf(bm, sred[q]); bc += scnt[q]; }
    if (bc > 0) {
      int si = __float_as_int(bm);
      unsigned enc = (unsigned)si ^ (((unsigned)(si >> 31)) | 0x80000000u);
      atomicMax(&g_gmax_u, enc);
    }
    atomicAdd(&g_cnt, bc);
    __threadfence();
    last = (atomicAdd(&g_blocks_done, 1) == SCAN_BLK - 1);
    sred[0] = (float)last;
  }
  __syncthreads();
  if (sred[0] == 0.0f) return;
  __threadfence();                           // acquire scores/legal/max/cnt

  unsigned genc = g_gmax_u;
  int cnt = g_cnt;
  int gs = (genc & 0x80000000u) ? (int)(genc ^ 0x80000000u) : (int)(~genc);
  float gm = __int_as_float(gs);

  float sum = 0.0f;
  int q0 = tid * (KSAMP / SCAN_TPB);         // 32 samples per thread
#pragma unroll
  for (int q = 0; q < KSAMP / SCAN_TPB; q += 4) {
    float4 sc = *(const float4*)(g_score + q0 + q);
    uchar4 lg = *(const uchar4*)(g_legal + q0 + q);
    if (lg.x) sum += __expf(sc.x - gm);
    if (lg.y) sum += __expf(sc.y - gm);
    if (lg.z) sum += __expf(sc.z - gm);
    if (lg.w) sum += __expf(sc.w - gm);
  }
  __syncthreads();
  sred[tid] = sum; __syncthreads();
  for (int st = SCAN_TPB / 2; st > 0; st >>= 1) {
    if (tid < st) sred[tid] += sred[tid + st];
    __syncthreads();
  }

  if (tid == 0) {
    float lse = gm + logf(sred[0]);
    double log_all = lgamma(21.0) + log(1767263190.0) + 19.0 * log(3.0);
    double res = log_all + (double)logf((float)cnt) - 2.0 * log(4096.0) + (double)lse;
    out[0] = (float)res;
    g_blocks_done = 0;                       // reset for next graph replay
    g_cnt = 0;
    g_gmax_u = 0u;
  }
}

// ---------------- Launch ------------------------------------------------------
extern "C" void kernel_launch(void* const* d_in, const int* in_sizes, int n_in,
                              void* d_out, int out_size) {
  const int*   ids = (const int*)d_in[0];
  const float* emb = (const float*)d_in[1];
  const float* lv  = (const float*)d_in[2];
  const float* fx  = (const float*)d_in[3];
  const float* Wf  = (const float*)d_in[4];
  const float* Wa  = (const float*)d_in[5];
  const float* bop = (const float*)d_in[6];
  float* out = (float*)d_out;

  // jax.random.key(42) -> (0,42); partitionable foldlike split
  uint32_t kop0, kop1, kg0, kg1;
  tf_block(0u, 42u, 0u, 0u, &kop0, &kop1);
  tf_block(0u, 42u, 0u, 1u, &kg0, &kg1);

  keygen_kernel<<<dim3(ROWN / 256, NSTEP + 1), 256>>>(kg0, kg1, kop0, kop1,
                                                      ids, emb, lv, fx, Wf, Wa, bop);
  scan_kernel<<<SCAN_BLK, SCAN_TPB>>>(out);
}

// round 11
// speedup vs baseline: 1.3222x; 1.0754x over previous
#include <cuda_runtime.h>
#include <math.h>
#include <stdint.h>

#define NTOK   20
#define DVEC   256
#define KSAMP  4096
#define NSTEP  19
#define WPB    4                   /* warps per block */
#define SPW    8                   /* samples per warp (4 lanes each) */
#define BSAMP  (WPB*SPW)           /* 32 samples per block */
#define NBLK   (KSAMP/BSAMP)       /* 128 blocks */
#define TPB    (WPB*32)            /* 128 threads */

__device__ float          g_score[KSAMP];
__device__ unsigned char  g_legal[KSAMP];
__device__ unsigned int   g_gmax_u = 0;       // int-mapped float max (reset)
__device__ int            g_cnt = 0;          // legal count (reset)
__device__ int            g_blocks_done = 0;  // reset by last block

// ---------------- Threefry-2x32 (20 rounds), identical to JAX ----------------
__host__ __device__ __forceinline__ void tf_block(uint32_t k0, uint32_t k1,
                                                  uint32_t x0, uint32_t x1,
                                                  uint32_t* o0, uint32_t* o1) {
  uint32_t ks2 = k0 ^ k1 ^ 0x1BD11BDAu;
  x0 += k0; x1 += k1;
#define TF_ROT(r) { x0 += x1; x1 = (x1 << (r)) | (x1 >> (32 - (r))); x1 ^= x0; }
  TF_ROT(13) TF_ROT(15) TF_ROT(26) TF_ROT(6)
  x0 += k1;  x1 += ks2 + 1u;
  TF_ROT(17) TF_ROT(29) TF_ROT(16) TF_ROT(24)
  x0 += ks2; x1 += k0 + 2u;
  TF_ROT(13) TF_ROT(15) TF_ROT(26) TF_ROT(6)
  x0 += k0;  x1 += k1 + 3u;
  TF_ROT(17) TF_ROT(29) TF_ROT(16) TF_ROT(24)
  x0 += k1;  x1 += ks2 + 4u;
  TF_ROT(13) TF_ROT(15) TF_ROT(26) TF_ROT(6)
  x0 += ks2; x1 += k0 + 5u;
#undef TF_ROT
  *o0 = x0; *o1 = x1;
}

__device__ __forceinline__ uint32_t tf_bits32(uint32_t k0, uint32_t k1, uint32_t i) {
  uint32_t a, b;
  tf_block(k0, k1, 0u, i, &a, &b);
  return a ^ b;
}

// ---------------- warp-per-token prep into smem (shuffle-only) ----------------
__device__ __forceinline__ void prep_token_smem(int i, int lane, float* sS,
                                                const int* __restrict__ ids,
                                                const float* __restrict__ emb,
                                                const float* __restrict__ lv,
                                                const float* __restrict__ fx,
                                                const float* __restrict__ Wf,
                                                const float* __restrict__ Wa,
                                                const float* __restrict__ bop) {
  const unsigned FULL = 0xFFFFFFFFu;
  int id = ids[i];
  const float4* er = (const float4*)(emb + (size_t)id * DVEC);
  const float4* fr = (const float4*)(fx  + (size_t)id * DVEC);
  float4 e0 = er[lane * 2], e1 = er[lane * 2 + 1];
  float4 f0 = fr[lane * 2], f1 = fr[lane * 2 + 1];
  float lvv = lv[id];

  float ev[8] = {e0.x, e0.y, e0.z, e0.w, e1.x, e1.y, e1.z, e1.w};
  float fv[8] = {f0.x, f0.y, f0.z, f0.w, f1.x, f1.y, f1.z, f1.w};

  float m = ev[0];
#pragma unroll
  for (int j = 1; j < 8; j++) m = fmaxf(m, ev[j]);
#pragma unroll
  for (int o = 16; o; o >>= 1) m = fmaxf(m, __shfl_xor_sync(FULL, m, o));

  float ex[8]; float sm = 0.0f;
#pragma unroll
  for (int j = 0; j < 8; j++) { ex[j] = expf(ev[j] - m); sm += ex[j]; }
#pragma unroll
  for (int o = 16; o; o >>= 1) sm += __shfl_xor_sync(FULL, sm, o);

  float x[8];
#pragma unroll
  for (int j = 0; j < 8; j++) x[j] = (ex[j] / sm) * lvv + fv[j];

  float p[6] = {0, 0, 0, 0, 0, 0};
#pragma unroll
  for (int j = 0; j < 8; j++) {
    int d = lane * 8 + j;
    p[0] += x[j] * Wf[d * 3 + 0];
    p[1] += x[j] * Wf[d * 3 + 1];
    p[2] += x[j] * Wf[d * 3 + 2];
    p[3] += x[j] * Wa[d * 3 + 0];
    p[4] += x[j] * Wa[d * 3 + 1];
    p[5] += x[j] * Wa[d * 3 + 2];
  }
#pragma unroll
  for (int o = 16; o; o >>= 1) {
#pragma unroll
    for (int q = 0; q < 6; q++) p[q] += __shfl_xor_sync(FULL, p[q], o);
  }
  if (lane == 0) {
#pragma unroll
    for (int q = 0; q < 6; q++)
      sS[i * 6 + q] = p[q] + (q < 3 ? bop[q] : 0.0f);
  }
}

// ---------------- single fused kernel -----------------------------------------
__global__ __launch_bounds__(TPB) void fused_kernel(
    uint32_t kop0, uint32_t kop1, uint32_t kg0, uint32_t kg1,
    const int* __restrict__ ids, const float* __restrict__ emb,
    const float* __restrict__ lv, const float* __restrict__ fx,
    const float* __restrict__ Wf, const float* __restrict__ Wa,
    const float* __restrict__ bop, float* __restrict__ out) {
  // per-warp key half-buffer: [t(10)][j(20)][lk(8)] words, warp-private
  __shared__ uint32_t      key_s[WPB][1600];
  __shared__ unsigned char ops_s[WPB][SPW][20];
  __shared__ float         sS[NTOK * 6];
  __shared__ float         sred[TPB];
  __shared__ int           scnt[WPB];

  const unsigned FULL = 0xFFFFFFFFu;
  int tid = threadIdx.x;
  int lane = tid & 31, w = tid >> 5;
  int samp = lane >> 2;                 // 0..7  (sample within warp)
  int s = lane & 3;                     // sub-lane 0..3
  int j0 = s * 5;                       // first owned slot
  int k0w = blockIdx.x * BSAMP + w * SPW;
  int k = k0w + samp;                   // this lane's sample

  // ---- Phase A: prep (block-redundant; each warp 5 tokens) -> sS ----
#pragma unroll
  for (int q = 0; q < 5; q++)
    prep_token_smem(w * 5 + q, lane, sS, ids, emb, lv, fx, Wf, Wa, bop);

  // ---- Phase B0: ops for this warp's 8 samples ----
#pragma unroll
  for (int f = 0; f < 160; f += 32) {
    int ff = f + lane;
    int t = ff >> 3, lk = ff & 7;       // t 0..19 (19 unused downstream)
    uint32_t bits = tf_bits32(kop0, kop1, (uint32_t)(t * KSAMP + k0w + lk));
    uint32_t op = ((bits >> 16) % 3u + (bits & 0xFFFFu) % 3u) % 3u;
    ops_s[w][lk][t] = (unsigned char)op;
  }

  // ---- Phase B1: keys for t = 0..9 (warp-private) ----
#pragma unroll 5
  for (int f = lane; f < 1600; f += 32) {
    int t = f / 160, rem = f - t * 160;
    int j = rem >> 3, lk = rem & 7;
    uint32_t ctr = (uint32_t)t * 81920u + (uint32_t)(k0w + lk) * 20u + (uint32_t)j;
    uint32_t key = tf_bits32(kg0, kg1, ctr) >> 9;   // gumbel order == bits>>9
    key_s[w][f] = ((key + 1u) << 5) | (31u - (uint32_t)j);
  }
  __syncthreads();                      // sS (cross-warp) + ops/keys ready

  // this lane's sample ops (5 u32 = 20 bytes)
  uint32_t ow[5];
  {
    const uint32_t* p = (const uint32_t*)ops_s[w][samp];
#pragma unroll
    for (int q = 0; q < 5; q++) ow[q] = p[q];
  }

  unsigned avail = 0xFFFFFu, f1 = 0u, f2 = 0u;
  unsigned long long plo = 0ull, phi = 0ull;   // ptr[20], 5 bits/slot
#pragma unroll
  for (int j = 0; j < 12; j++) plo |= (unsigned long long)j << (5 * j);
#pragma unroll
  for (int j = 12; j < 20; j++) phi |= (unsigned long long)j << (5 * (j - 12));

  float score = 0.0f;
  bool legal = true;

#define SCAN_STEP(T, TT)                                                        \
  {                                                                             \
    uint32_t u1 = 0u, u2 = 0u;                                                  \
    _Pragma("unroll")                                                           \
    for (int i = 0; i < 5; i++) {                                               \
      uint32_t v = ((avail >> (j0 + i)) & 1u)                                   \
                 ? key_s[w][(TT) * 160 + (j0 + i) * 8 + samp] : 0u;             \
      uint32_t mn = min(u1, v);                                                 \
      u1 = max(u1, v);                                                          \
      u2 = max(u2, mn);                                                         \
    }                                                                           \
    _Pragma("unroll")                                                           \
    for (int o = 1; o <= 2; o <<= 1) {                                          \
      uint32_t o1 = __shfl_xor_sync(FULL, u1, o);                               \
      uint32_t o2 = __shfl_xor_sync(FULL, u2, o);                               \
      uint32_t lo = min(u1, o1);                                                \
      u1 = max(u1, o1);                                                         \
      u2 = max(lo, max(u2, o2));                                                \
    }                                                                           \
    int b1 = (int)((~u1) & 31u), b2 = (int)((~u2) & 31u);                       \
    avail &= ~(1u << b2);                                                       \
    int op = (int)((ow[(T) >> 2] >> (((T) & 3) * 8)) & 3u);                     \
    int s1 = 5 * b1, s2 = 5 * b2;                                               \
    int s1l = (s1 < 60) ? s1 : 0,  s1h = (s1 >= 60) ? s1 - 60 : 0;              \
    int s2l = (s2 < 60) ? s2 : 0,  s2h = (s2 >= 60) ? s2 - 60 : 0;              \
    int pf = (int)((b1 < 12 ? (plo >> s1l) : (phi >> s1h)) & 31ull);            \
    int pa = (int)((b2 < 12 ? (plo >> s2l) : (phi >> s2h)) & 31ull);            \
    if (s == 0) score += sS[pf * 6 + op] + sS[pa * 6 + 3 + op];                 \
    unsigned of1 = (f1 >> b1) & 1u;                                             \
    unsigned of2 = (f2 >> b1) & 1u;                                             \
    bool bad = ((op != 2) && of1) || ((op == 1) && of2);                        \
    legal = legal && !bad;                                                      \
    if (op == 2) {                                                              \
      if (b1 < 12) plo = (plo & ~(31ull << s1l)) | ((unsigned long long)pa << s1l); \
      else         phi = (phi & ~(31ull << s1h)) | ((unsigned long long)pa << s1h); \
      unsigned a1 = (f1 >> b2) & 1u, a2 = (f2 >> b2) & 1u;                      \
      f1 = (f1 & ~(1u << b1)) | (a1 << b1);                                     \
      f2 = (f2 & ~(1u << b1)) | (a2 << b1);                                     \
    } else if (op == 0) {                                                       \
      f1 |= 1u << b1;                                                           \
    } else {                                                                    \
      f2 |= 1u << b1;                                                           \
    }                                                                           \
  }

  // ---- scan steps 0..9 from half-buffer ----
#pragma unroll
  for (int t = 0; t < 10; t++) SCAN_STEP(t, t)

  // ---- Phase B2: regen keys t = 10..18 (warp-private overwrite) ----
  __syncwarp();
#pragma unroll 5
  for (int f = lane; f < 1440; f += 32) {
    int t = f / 160, rem = f - t * 160;
    int j = rem >> 3, lk = rem & 7;
    uint32_t ctr = (uint32_t)(t + 10) * 81920u + (uint32_t)(k0w + lk) * 20u + (uint32_t)j;
    uint32_t key = tf_bits32(kg0, kg1, ctr) >> 9;
    key_s[w][f] = ((key + 1u) << 5) | (31u - (uint32_t)j);
  }
  __syncwarp();

  // ---- scan steps 10..18 ----
#pragma unroll
  for (int t = 10; t < NSTEP; t++) SCAN_STEP(t, t - 10)
#undef SCAN_STEP

  if (s == 0) {
    g_score[k] = score;
    g_legal[k] = legal ? 1 : 0;
  }

  // ---- warp/block partials -> global atomics ----
  float lm = (s == 0 && legal) ? score : -INFINITY;
  int lc = (s == 0 && legal) ? 1 : 0;
#pragma unroll
  for (int o = 16; o; o >>= 1) {
    lm = fmaxf(lm, __shfl_xor_sync(FULL, lm, o));
    lc += __shfl_xor_sync(FULL, lc, o);
  }
  if (lane == 0) { sred[w] = lm; scnt[w] = lc; }
  __syncthreads();
  if (tid == 0) {
    float bm = sred[0]; int bc = scnt[0];
#pragma unroll
    for (int q = 1; q < WPB; q++) { bm = fmaxf(bm, sred[q]); bc += scnt[q]; }
    if (bc > 0) {
      int si = __float_as_int(bm);
      unsigned enc = (unsigned)si ^ (((unsigned)(si >> 31)) | 0x80000000u);
      atomicMax(&g_gmax_u, enc);
    }
    atomicAdd(&g_cnt, bc);
    __threadfence();
    int last = (atomicAdd(&g_blocks_done, 1) == NBLK - 1);
    sred[0] = (float)last;
  }
  __syncthreads();
  if (sred[0] == 0.0f) return;
  __threadfence();                      // acquire scores/legal/max/cnt

  unsigned genc = g_gmax_u;
  int cnt = g_cnt;
  int gs = (genc & 0x80000000u) ? (int)(genc ^ 0x80000000u) : (int)(~genc);
  float gm = __int_as_float(gs);

  float sum = 0.0f;
  int q0 = tid * (KSAMP / TPB);         // 32 samples per thread
#pragma unroll
  for (int q = 0; q < KSAMP / TPB; q += 4) {
    float4 sc = *(const float4*)(g_score + q0 + q);
    uchar4 lg = *(const uchar4*)(g_legal + q0 + q);
    if (lg.x) sum += __expf(sc.x - gm);
    if (lg.y) sum += __expf(sc.y - gm);
    if (lg.z) sum += __expf(sc.z - gm);
    if (lg.w) sum += __expf(sc.w - gm);
  }
  __syncthreads();
  sred[tid] = sum; __syncthreads();
  for (int st = TPB / 2; st > 0; st >>= 1) {
    if (tid < st) sred[tid] += sred[tid + st];
    __syncthreads();
  }

  if (tid == 0) {
    float lse = gm + logf(sred[0]);
    double log_all = lgamma(21.0) + log(1767263190.0) + 19.0 * log(3.0);
    double res = log_all + (double)logf((float)cnt) - 2.0 * log(4096.0) + (double)lse;
    out[0] = (float)res;
    g_blocks_done = 0;                  // reset for next graph replay
    g_cnt = 0;
    g_gmax_u = 0u;
  }
}

// ---------------- Launch ------------------------------------------------------
extern "C" void kernel_launch(void* const* d_in, const int* in_sizes, int n_in,
                              void* d_out, int out_size) {
  const int*   ids = (const int*)d_in[0];
  const float* emb = (const float*)d_in[1];
  const float* lv  = (const float*)d_in[2];
  const float* fx  = (const float*)d_in[3];
  const float* Wf  = (const float*)d_in[4];
  const float* Wa  = (const float*)d_in[5];
  const float* bop = (const float*)d_in[6];
  float* out = (float*)d_out;

  // jax.random.key(42) -> (0,42); partitionable foldlike split
  uint32_t kop0, kop1, kg0, kg1;
  tf_block(0u, 42u, 0u, 0u, &kop0, &kop1);
  tf_block(0u, 42u, 0u, 1u, &kg0, &kg1);

  fused_kernel<<<NBLK, TPB>>>(kop0, kop1, kg0, kg1,
                              ids, emb, lv, fx, Wf, Wa, bop, out);
}